// round 1
// baseline (speedup 1.0000x reference)
#include <cuda_runtime.h>
#include <cuda_bf16.h>
#include <math.h>

// Problem constants
#define NN      4096
#define IN_DIM  256
#define CCH     8
#define DD      64
#define CD      512     // C*D
#define OUTD    128
#define EDGE_CAP (1 << 20)

// ---------------- device scratch (no allocations allowed) ----------------
__device__ int   g_cnt[NN];
__device__ int   g_rowptr[NN + 1];
__device__ int   g_colidx[EDGE_CAP];
__device__ float g_Bmat[IN_DIM * CD];        // W transposed to [256, 512]
__device__ float g_zA[(size_t)NN * CD];      // ping
__device__ float g_zB[(size_t)NN * CD];      // pong

// ---------------- CSR build ----------------
// one warp per row, count nonzeros
__global__ void count_rows(const float* __restrict__ adj) {
    int row  = blockIdx.x * 8 + (threadIdx.x >> 5);
    int lane = threadIdx.x & 31;
    const float* r = adj + (size_t)row * NN;
    int c = 0;
    for (int j = lane; j < NN; j += 32) c += (r[j] > 0.0f);
#pragma unroll
    for (int off = 16; off; off >>= 1) c += __shfl_xor_sync(0xffffffffu, c, off);
    if (lane == 0) g_cnt[row] = c;
}

// single-block exclusive scan of 4096 counts -> rowptr
__global__ void scan_rows() {
    __shared__ int sdata[1024];
    int tid = threadIdx.x;
    int a0 = g_cnt[tid * 4 + 0];
    int a1 = g_cnt[tid * 4 + 1];
    int a2 = g_cnt[tid * 4 + 2];
    int a3 = g_cnt[tid * 4 + 3];
    int sum = a0 + a1 + a2 + a3;
    sdata[tid] = sum;
    __syncthreads();
    for (int off = 1; off < 1024; off <<= 1) {
        int v = 0;
        if (tid >= off) v = sdata[tid - off];
        __syncthreads();
        sdata[tid] += v;
        __syncthreads();
    }
    int ex = sdata[tid] - sum;   // exclusive prefix
    g_rowptr[tid * 4 + 0] = ex;
    g_rowptr[tid * 4 + 1] = ex + a0;
    g_rowptr[tid * 4 + 2] = ex + a0 + a1;
    g_rowptr[tid * 4 + 3] = ex + a0 + a1 + a2;
    if (tid == 1023) g_rowptr[NN] = sdata[1023];
}

// one warp per row, ordered ballot compaction -> deterministic edge order
__global__ void fill_rows(const float* __restrict__ adj) {
    int row  = blockIdx.x * 8 + (threadIdx.x >> 5);
    int lane = threadIdx.x & 31;
    const float* r = adj + (size_t)row * NN;
    int base = g_rowptr[row];
    for (int j0 = 0; j0 < NN; j0 += 32) {
        int j = j0 + lane;
        bool v = r[j] > 0.0f;
        unsigned m = __ballot_sync(0xffffffffu, v);
        if (v) {
            int pos = base + __popc(m & ((1u << lane) - 1u));
            if (pos < EDGE_CAP) g_colidx[pos] = j;
        }
        base += __popc(m);
    }
}

// ---------------- W [8,256,64] -> Bmat [256, 512] (col = c*64+d) ----------------
__global__ void build_B(const float* __restrict__ W) {
    int idx = blockIdx.x * 256 + threadIdx.x;   // 131072 total
    int c   = idx >> 14;         // / (256*64)
    int rem = idx & 16383;
    int i   = rem >> 6;
    int d   = rem & 63;
    g_Bmat[(size_t)i * CD + c * DD + d] = W[idx];
}

// ---------------- generic fp32 tiled GEMM + column bias ----------------
// C[M,N] = A[M,K] @ B[K,N] + bias[N].  BM=BN=64, BK=16, 256 threads, 4x4/thread.
// Requires M%64==0, N%64==0, K%16==0.
__global__ void __launch_bounds__(256) gemm_bias(
    const float* __restrict__ A, const float* __restrict__ B,
    const float* __restrict__ bias, float* __restrict__ Cd,
    int M, int N, int K)
{
    __shared__ float As[16][65];
    __shared__ float Bs[16][64];
    int tid = threadIdx.x;
    int rowBase = blockIdx.y * 64;
    int colBase = blockIdx.x * 64;
    int tx = tid & 15, ty = tid >> 4;
    int a_r = tid >> 2;           // 0..63
    int a_k = (tid & 3) * 4;      // 0,4,8,12
    int b_k = tid >> 4;           // 0..15
    int b_n = (tid & 15) * 4;
    float acc[4][4] = {};
    for (int k0 = 0; k0 < K; k0 += 16) {
        float4 av = *reinterpret_cast<const float4*>(
            A + (size_t)(rowBase + a_r) * K + k0 + a_k);
        As[a_k + 0][a_r] = av.x;
        As[a_k + 1][a_r] = av.y;
        As[a_k + 2][a_r] = av.z;
        As[a_k + 3][a_r] = av.w;
        float4 bv = *reinterpret_cast<const float4*>(
            B + (size_t)(k0 + b_k) * N + colBase + b_n);
        *reinterpret_cast<float4*>(&Bs[b_k][b_n]) = bv;
        __syncthreads();
#pragma unroll
        for (int kk = 0; kk < 16; ++kk) {
            float ar[4], br[4];
#pragma unroll
            for (int u = 0; u < 4; ++u) ar[u] = As[kk][ty * 4 + u];
#pragma unroll
            for (int u = 0; u < 4; ++u) br[u] = Bs[kk][tx * 4 + u];
#pragma unroll
            for (int mi = 0; mi < 4; ++mi)
#pragma unroll
                for (int ni = 0; ni < 4; ++ni)
                    acc[mi][ni] = fmaf(ar[mi], br[ni], acc[mi][ni]);
        }
        __syncthreads();
    }
#pragma unroll
    for (int mi = 0; mi < 4; ++mi) {
        int r = rowBase + ty * 4 + mi;
#pragma unroll
        for (int ni = 0; ni < 4; ++ni) {
            int cidx = colBase + tx * 4 + ni;
            Cd[(size_t)r * N + cidx] = acc[mi][ni] + bias[cidx];
        }
    }
}

// ---------------- per-node per-channel l2 normalize, in place ----------------
__global__ void __launch_bounds__(512) l2norm_k(float* __restrict__ z) {
    int n   = blockIdx.x;
    int tid = threadIdx.x;          // (c,d) = (tid>>6, tid&63)
    int lane = tid & 31, warp = tid >> 5, c = tid >> 6;
    __shared__ float sp[16];
    float v = z[(size_t)n * CD + tid];
    float ss = v * v;
#pragma unroll
    for (int off = 16; off; off >>= 1) ss += __shfl_xor_sync(0xffffffffu, ss, off);
    if (lane == 0) sp[warp] = ss;
    __syncthreads();
    float tot = sp[c * 2] + sp[c * 2 + 1];
    z[(size_t)n * CD + tid] = v * rsqrtf(fmaxf(tot, 1e-12f));
}

// ---------------- fused routing iteration ----------------
// per row i (block), per edge j: s[c] = <z[c][i], z[c][j]>, a = softmax_c(s),
// acc += a_c * z[c][j]; then z_new = l2norm(z[i] + acc).
__global__ void __launch_bounds__(512) route_iter(int flip) {
    const float* __restrict__ zsrc = flip ? g_zB : g_zA;
    float* __restrict__ zdst       = flip ? g_zA : g_zB;
    int i    = blockIdx.x;
    int tid  = threadIdx.x;         // 512: c = tid>>6, d = tid&63
    int lane = tid & 31;
    int warp = tid >> 5;            // channel c = warp>>1
    int c    = tid >> 6;
    __shared__ float s_part[16];
    __shared__ float s_a[8];

    float zi  = zsrc[(size_t)i * CD + tid];
    float acc = 0.0f;
    int beg = g_rowptr[i], end = g_rowptr[i + 1];

    // prefetch first neighbor
    float zjn = 0.0f;
    if (beg < end) {
        int j0 = g_colidx[beg];
        zjn = zsrc[(size_t)j0 * CD + tid];
    }
    for (int e = beg; e < end; ++e) {
        float zj = zjn;
        if (e + 1 < end) {                       // prefetch next (hides L2 latency)
            int j2 = g_colidx[e + 1];
            zjn = zsrc[(size_t)j2 * CD + tid];
        }
        float p = zi * zj;
#pragma unroll
        for (int off = 16; off; off >>= 1) p += __shfl_xor_sync(0xffffffffu, p, off);
        if (lane == 0) s_part[warp] = p;
        __syncthreads();
        if (warp == 0) {                         // 8-way channel softmax in warp 0
            int cc = lane & 7;
            float v = s_part[2 * cc] + s_part[2 * cc + 1];
            float m = v;
#pragma unroll
            for (int off = 4; off; off >>= 1)
                m = fmaxf(m, __shfl_xor_sync(0xffffffffu, m, off));
            float ex = __expf(v - m);
            float s = ex;
#pragma unroll
            for (int off = 4; off; off >>= 1)
                s += __shfl_xor_sync(0xffffffffu, s, off);
            if (lane < 8) s_a[lane] = ex / s;
        }
        __syncthreads();
        acc = fmaf(s_a[c], zj, acc);
    }

    // residual + l2norm
    float zn = zi + acc;
    float ss = zn * zn;
#pragma unroll
    for (int off = 16; off; off >>= 1) ss += __shfl_xor_sync(0xffffffffu, ss, off);
    if (lane == 0) s_part[warp] = ss;
    __syncthreads();
    float tot = s_part[c * 2] + s_part[c * 2 + 1];
    zdst[(size_t)i * CD + tid] = zn * rsqrtf(fmaxf(tot, 1e-12f));
}

// ---------------- launch ----------------
extern "C" void kernel_launch(void* const* d_in, const int* in_sizes, int n_in,
                              void* d_out, int out_size) {
    const float* features = (const float*)d_in[0];   // [4096,256]
    const float* adj      = (const float*)d_in[1];   // [4096,4096]
    const float* W        = (const float*)d_in[2];   // [8,256,64]
    const float* bvec     = (const float*)d_in[3];   // [8,1,64] -> flat [512]
    const float* W_o      = (const float*)d_in[4];   // [512,128]
    const float* bias     = (const float*)d_in[5];   // [1,128]
    float* out            = (float*)d_out;           // [4096,128]

    float *pB = nullptr, *pzA = nullptr;
    cudaGetSymbolAddress((void**)&pB,  g_Bmat);
    cudaGetSymbolAddress((void**)&pzA, g_zA);

    // CSR from adjacency (deterministic, ordered)
    count_rows<<<NN / 8, 256>>>(adj);
    scan_rows<<<1, 1024>>>();
    fill_rows<<<NN / 8, 256>>>(adj);

    // projection: z0 = features @ Bmat + b, then l2norm per (n,c)
    build_B<<<(CCH * IN_DIM * DD) / 256, 256>>>(W);
    gemm_bias<<<dim3(CD / 64, NN / 64), 256>>>(features, pB, bvec, pzA,
                                               NN, CD, IN_DIM);
    l2norm_k<<<NN, 512>>>(pzA);

    // 4 fused routing iterations (ping-pong zA <-> zB, final lands in zA)
    route_iter<<<NN, 512>>>(0);
    route_iter<<<NN, 512>>>(1);
    route_iter<<<NN, 512>>>(0);
    route_iter<<<NN, 512>>>(1);

    // output: h @ W_o + bias   (h == zA layout [N, C*D])
    gemm_bias<<<dim3(OUTD / 64, NN / 64), 256>>>(pzA, W_o, bias, out,
                                                 NN, OUTD, CD);
}

// round 2
// speedup vs baseline: 3.0471x; 3.0471x over previous
#include <cuda_runtime.h>
#include <math.h>

#define NN      4096
#define IN_DIM  256
#define CD      512
#define OUTD    128
#define EDGE_CAP (1 << 20)

// ---------------- device scratch (no allocations allowed) ----------------
__device__ int   g_cnt[NN];
__device__ int   g_rowptr[NN + 1];
__device__ int   g_colidx[EDGE_CAP];
__device__ float g_zA[(size_t)NN * CD];
__device__ float g_zB[(size_t)NN * CD];   // ping-pong; also reused as split-K partial buf (4MB of 8MB)

// ---------------- CSR build ----------------
__global__ void count_rows(const float* __restrict__ adj) {
    int row  = blockIdx.x * 8 + (threadIdx.x >> 5);
    int lane = threadIdx.x & 31;
    const float* r = adj + (size_t)row * NN;
    int c = 0;
    for (int j = lane; j < NN; j += 32) c += (r[j] > 0.0f);
#pragma unroll
    for (int off = 16; off; off >>= 1) c += __shfl_xor_sync(0xffffffffu, c, off);
    if (lane == 0) g_cnt[row] = c;
}

__global__ void scan_rows() {
    __shared__ int sdata[1024];
    int tid = threadIdx.x;
    int a0 = g_cnt[tid * 4 + 0];
    int a1 = g_cnt[tid * 4 + 1];
    int a2 = g_cnt[tid * 4 + 2];
    int a3 = g_cnt[tid * 4 + 3];
    int sum = a0 + a1 + a2 + a3;
    sdata[tid] = sum;
    __syncthreads();
    for (int off = 1; off < 1024; off <<= 1) {
        int v = 0;
        if (tid >= off) v = sdata[tid - off];
        __syncthreads();
        sdata[tid] += v;
        __syncthreads();
    }
    int ex = sdata[tid] - sum;
    g_rowptr[tid * 4 + 0] = ex;
    g_rowptr[tid * 4 + 1] = ex + a0;
    g_rowptr[tid * 4 + 2] = ex + a0 + a1;
    g_rowptr[tid * 4 + 3] = ex + a0 + a1 + a2;
    if (tid == 1023) g_rowptr[NN] = sdata[1023];
}

__global__ void fill_rows(const float* __restrict__ adj) {
    int row  = blockIdx.x * 8 + (threadIdx.x >> 5);
    int lane = threadIdx.x & 31;
    const float* r = adj + (size_t)row * NN;
    int base = g_rowptr[row];
    for (int j0 = 0; j0 < NN; j0 += 32) {
        int j = j0 + lane;
        bool v = r[j] > 0.0f;
        unsigned m = __ballot_sync(0xffffffffu, v);
        if (v) {
            int pos = base + __popc(m & ((1u << lane) - 1u));
            if (pos < EDGE_CAP) g_colidx[pos] = j;
        }
        base += __popc(m);
    }
}

// ---------------- GEMM: C[M,N] = A[M,K] @ B + bias, BM=128 BN=64 BK=16 ----------------
// MODE 0: B is dense row-major [K,N].
// MODE 1: B column col=c*64+d, row k comes from W[c,k,d] (c=col>>6, d=col&63).
// gridDim.z>1: split-K, write partials (no bias) to Cpart[z][M][N].
template <int MODE>
__global__ void __launch_bounds__(256) gemm128x64(
    const float* __restrict__ A, const float* __restrict__ B,
    const float* __restrict__ bias, float* __restrict__ C,
    float* __restrict__ Cpart, int M, int N, int K, int kSplit)
{
    __shared__ float As[16][132];
    __shared__ float Bs[16][64];
    int tid = threadIdx.x;
    int rowBase = blockIdx.y * 128;
    int colBase = blockIdx.x * 64;
    int kBeg = blockIdx.z * kSplit;
    int kEnd = kBeg + kSplit;
    int tx = tid & 15, ty = tid >> 4;
    float acc[8][4] = {};

    for (int k0 = kBeg; k0 < kEnd; k0 += 16) {
#pragma unroll
        for (int h = 0; h < 2; h++) {
            int F = tid + h * 256;          // float4 id within 128x16 A tile
            int r = F >> 2, q = F & 3;
            float4 av = *reinterpret_cast<const float4*>(
                A + (size_t)(rowBase + r) * K + k0 + q * 4);
            As[q * 4 + 0][r] = av.x;
            As[q * 4 + 1][r] = av.y;
            As[q * 4 + 2][r] = av.z;
            As[q * 4 + 3][r] = av.w;
        }
        {
            int kb = tid >> 4, c4 = tid & 15;
            int col = colBase + c4 * 4;
            const float* src;
            if (MODE == 1) {
                int c = col >> 6, d = col & 63;
                src = B + ((size_t)c << 14) + ((size_t)(k0 + kb) << 6) + d;
            } else {
                src = B + (size_t)(k0 + kb) * N + col;
            }
            *reinterpret_cast<float4*>(&Bs[kb][c4 * 4]) =
                *reinterpret_cast<const float4*>(src);
        }
        __syncthreads();
#pragma unroll
        for (int kk = 0; kk < 16; kk++) {
            float4 a0 = *reinterpret_cast<const float4*>(&As[kk][ty * 8]);
            float4 a1 = *reinterpret_cast<const float4*>(&As[kk][ty * 8 + 4]);
            float4 b0 = *reinterpret_cast<const float4*>(&Bs[kk][tx * 4]);
            float ar[8] = {a0.x, a0.y, a0.z, a0.w, a1.x, a1.y, a1.z, a1.w};
            float br[4] = {b0.x, b0.y, b0.z, b0.w};
#pragma unroll
            for (int mi = 0; mi < 8; mi++)
#pragma unroll
                for (int ni = 0; ni < 4; ni++)
                    acc[mi][ni] = fmaf(ar[mi], br[ni], acc[mi][ni]);
        }
        __syncthreads();
    }

    if (gridDim.z == 1) {
        float4 bv = *reinterpret_cast<const float4*>(bias + colBase + tx * 4);
#pragma unroll
        for (int mi = 0; mi < 8; mi++) {
            int r = rowBase + ty * 8 + mi;
            float4 o = make_float4(acc[mi][0] + bv.x, acc[mi][1] + bv.y,
                                   acc[mi][2] + bv.z, acc[mi][3] + bv.w);
            *reinterpret_cast<float4*>(C + (size_t)r * N + colBase + tx * 4) = o;
        }
    } else {
        float* P = Cpart + (size_t)blockIdx.z * M * N;
#pragma unroll
        for (int mi = 0; mi < 8; mi++) {
            int r = rowBase + ty * 8 + mi;
            float4 o = make_float4(acc[mi][0], acc[mi][1], acc[mi][2], acc[mi][3]);
            *reinterpret_cast<float4*>(P + (size_t)r * N + colBase + tx * 4) = o;
        }
    }
}

// split-K=2 reduce + bias (out [4096,128])
__global__ void reduce_bias(const float4* __restrict__ P,
                            const float4* __restrict__ bias,
                            float4* __restrict__ out)
{
    int i = blockIdx.x * 256 + threadIdx.x;   // NN*OUTD/4 = 131072
    if (i >= NN * OUTD / 4) return;
    float4 a = P[i];
    float4 b = P[i + NN * OUTD / 4];
    float4 bs = bias[i & (OUTD / 4 - 1)];
    out[i] = make_float4(a.x + b.x + bs.x, a.y + b.y + bs.y,
                         a.z + b.z + bs.z, a.w + b.w + bs.w);
}

// ---------------- per-(node,channel) l2 normalize, float4 / 128 threads ----------------
__global__ void __launch_bounds__(128) l2norm_k(float4* __restrict__ z) {
    int i = blockIdx.x, t = threadIdx.x;
    float4 v = z[(size_t)i * 128 + t];
    float ss = v.x * v.x + v.y * v.y + v.z * v.z + v.w * v.w;
#pragma unroll
    for (int off = 1; off <= 8; off <<= 1) ss += __shfl_xor_sync(0xffffffffu, ss, off);
    float sc = rsqrtf(fmaxf(ss, 1e-12f));
    z[(size_t)i * 128 + t] = make_float4(v.x * sc, v.y * sc, v.z * sc, v.w * sc);
}

// ---------------- fused routing iteration, batched 8 edges / 2 barriers ----------------
// 128 threads: thread t covers dims [4t, 4t+4) -> channel c = t>>4.
// Warp w covers channels 2w (lanes 0-15) and 2w+1 (lanes 16-31).
__global__ void __launch_bounds__(128) route_iter(const float4* __restrict__ zsrc,
                                                  float4* __restrict__ zdst)
{
    int i = blockIdx.x;
    int t = threadIdx.x;
    int lane = t & 31, w = t >> 5;
    int half = lane >> 4;
    int c = t >> 4;
    __shared__ float s_sc[8][8];   // [edge][channel] raw scores
    __shared__ float s_a[8][8];    // [edge][channel] softmax weights

    float4 zi = zsrc[(size_t)i * 128 + t];
    float4 acc = make_float4(0.f, 0.f, 0.f, 0.f);
    int beg = g_rowptr[i], end = g_rowptr[i + 1];

    for (int e0 = beg; e0 < end; e0 += 8) {
        int m = end - e0;
        float4 zj[8];
#pragma unroll
        for (int k = 0; k < 8; k++) {
            zj[k] = make_float4(0.f, 0.f, 0.f, 0.f);
            if (k < m) {
                int j = g_colidx[e0 + k];
                zj[k] = zsrc[(size_t)j * 128 + t];
            }
        }
        // per-channel dots: reduce within 16-lane half (4 shuffles), 8 edges
#pragma unroll
        for (int k = 0; k < 8; k++) {
            float p = zi.x * zj[k].x + zi.y * zj[k].y + zi.z * zj[k].z + zi.w * zj[k].w;
            p += __shfl_xor_sync(0xffffffffu, p, 1);
            p += __shfl_xor_sync(0xffffffffu, p, 2);
            p += __shfl_xor_sync(0xffffffffu, p, 4);
            p += __shfl_xor_sync(0xffffffffu, p, 8);
            if ((lane & 15) == k) s_sc[k][2 * w + half] = p;
        }
        __syncthreads();
        // 8-way channel softmax for 8 edges, all inside warp 0 (lane = e*4+g)
        if (w == 0) {
            int e = lane >> 2, g = lane & 3;
            float v0 = s_sc[e][2 * g], v1 = s_sc[e][2 * g + 1];
            float mx = fmaxf(v0, v1);
            mx = fmaxf(mx, __shfl_xor_sync(0xffffffffu, mx, 1));
            mx = fmaxf(mx, __shfl_xor_sync(0xffffffffu, mx, 2));
            float ex0 = __expf(v0 - mx), ex1 = __expf(v1 - mx);
            float sm = ex0 + ex1;
            sm += __shfl_xor_sync(0xffffffffu, sm, 1);
            sm += __shfl_xor_sync(0xffffffffu, sm, 2);
            float inv = 1.0f / sm;
            s_a[e][2 * g]     = ex0 * inv;
            s_a[e][2 * g + 1] = ex1 * inv;
        }
        __syncthreads();
        // aggregate (zj[k]=0 for invalid edges -> contributes nothing)
#pragma unroll
        for (int k = 0; k < 8; k++) {
            float a = s_a[k][c];
            acc.x = fmaf(a, zj[k].x, acc.x);
            acc.y = fmaf(a, zj[k].y, acc.y);
            acc.z = fmaf(a, zj[k].z, acc.z);
            acc.w = fmaf(a, zj[k].w, acc.w);
        }
        // no 3rd barrier: next batch writes s_sc (disjoint from s_a); s_a is
        // rewritten only after the next barrier pair.
    }

    // residual + l2norm (per channel = 16-lane half)
    float4 zn = make_float4(zi.x + acc.x, zi.y + acc.y, zi.z + acc.z, zi.w + acc.w);
    float ss = zn.x * zn.x + zn.y * zn.y + zn.z * zn.z + zn.w * zn.w;
    ss += __shfl_xor_sync(0xffffffffu, ss, 1);
    ss += __shfl_xor_sync(0xffffffffu, ss, 2);
    ss += __shfl_xor_sync(0xffffffffu, ss, 4);
    ss += __shfl_xor_sync(0xffffffffu, ss, 8);
    float sc = rsqrtf(fmaxf(ss, 1e-12f));
    zdst[(size_t)i * 128 + t] = make_float4(zn.x * sc, zn.y * sc, zn.z * sc, zn.w * sc);
}

// ---------------- launch ----------------
extern "C" void kernel_launch(void* const* d_in, const int* in_sizes, int n_in,
                              void* d_out, int out_size) {
    const float* features = (const float*)d_in[0];   // [4096,256]
    const float* adj      = (const float*)d_in[1];   // [4096,4096]
    const float* W        = (const float*)d_in[2];   // [8,256,64]
    const float* bvec     = (const float*)d_in[3];   // [8,1,64] flat [512]
    const float* W_o      = (const float*)d_in[4];   // [512,128]
    const float* bias     = (const float*)d_in[5];   // [1,128]
    float* out            = (float*)d_out;           // [4096,128]

    float *pzA = nullptr, *pzB = nullptr;
    cudaGetSymbolAddress((void**)&pzA, g_zA);
    cudaGetSymbolAddress((void**)&pzB, g_zB);

    // CSR (deterministic ordered compaction)
    count_rows<<<NN / 8, 256>>>(adj);
    scan_rows<<<1, 1024>>>();
    fill_rows<<<NN / 8, 256>>>(adj);

    // projection z0 = l2norm(features @ W + b), W read in-place (no repack)
    gemm128x64<1><<<dim3(CD / 64, NN / 128, 1), 256>>>(
        features, W, bvec, pzA, nullptr, NN, CD, IN_DIM, IN_DIM);
    l2norm_k<<<NN, 128>>>((float4*)pzA);

    // 4 fused routing iterations (ping-pong, final z in zA)
    route_iter<<<NN, 128>>>((const float4*)pzA, (float4*)pzB);
    route_iter<<<NN, 128>>>((const float4*)pzB, (float4*)pzA);
    route_iter<<<NN, 128>>>((const float4*)pzA, (float4*)pzB);
    route_iter<<<NN, 128>>>((const float4*)pzB, (float4*)pzA);

    // output GEMM, split-K=2 into g_zB, then reduce + bias
    gemm128x64<0><<<dim3(OUTD / 64, NN / 128, 2), 256>>>(
        pzA, W_o, nullptr, nullptr, pzB, NN, OUTD, CD, CD / 2);
    reduce_bias<<<(NN * OUTD / 4 + 255) / 256, 256>>>(
        (const float4*)pzB, (const float4*)bias, (float4*)out);
}

// round 3
// speedup vs baseline: 3.0501x; 1.0010x over previous
#include <cuda_runtime.h>
#include <math.h>

#define NN      4096
#define IN_DIM  256
#define CD      512
#define OUTD    128
#define PAD     128      // max neighbors kept per row (mean deg ~41, 13+ sigma headroom)

// ---------------- device scratch (no allocations allowed) ----------------
__device__ int   g_cnt[NN];
__device__ int   g_colpad[NN * PAD];
__device__ float g_zA[(size_t)NN * CD];
__device__ float g_zB[(size_t)NN * CD];
__device__ float g_part[(size_t)2 * NN * CD];   // split-K partials (16MB), reused by both GEMMs

// ---------------- single-pass adjacency -> padded column lists ----------------
// one warp per row: ordered ballot compaction, single DRAM pass over adj.
__global__ void build_adj(const float* __restrict__ adj) {
    int row  = blockIdx.x * 8 + (threadIdx.x >> 5);
    int lane = threadIdx.x & 31;
    const float* r = adj + (size_t)row * NN;
    int* dst = g_colpad + row * PAD;
    int base = 0;
    for (int j0 = 0; j0 < NN; j0 += 32) {
        int j = j0 + lane;
        bool v = r[j] > 0.0f;
        unsigned m = __ballot_sync(0xffffffffu, v);
        if (v) {
            int pos = base + __popc(m & ((1u << lane) - 1u));
            if (pos < PAD) dst[pos] = j;
        }
        base += __popc(m);
    }
    if (lane == 0) g_cnt[row] = base < PAD ? base : PAD;
}

// ---------------- GEMM: C[M,N] = A[M,K] @ B, BM=128 BN=64 BK=16, split-K ----------------
// MODE 0: B dense row-major [K,N].
// MODE 1: B column col=c*64+d maps to W[c,k,d].
// Always writes partials (no bias) to Cpart[z][M][N].
template <int MODE>
__global__ void __launch_bounds__(256) gemm128x64(
    const float* __restrict__ A, const float* __restrict__ B,
    float* __restrict__ Cpart, int M, int N, int K, int kSplit)
{
    __shared__ float As[16][132];
    __shared__ float Bs[16][64];
    int tid = threadIdx.x;
    int rowBase = blockIdx.y * 128;
    int colBase = blockIdx.x * 64;
    int kBeg = blockIdx.z * kSplit;
    int kEnd = kBeg + kSplit;
    int tx = tid & 15, ty = tid >> 4;
    float acc[8][4] = {};

    for (int k0 = kBeg; k0 < kEnd; k0 += 16) {
#pragma unroll
        for (int h = 0; h < 2; h++) {
            int F = tid + h * 256;
            int r = F >> 2, q = F & 3;
            float4 av = *reinterpret_cast<const float4*>(
                A + (size_t)(rowBase + r) * K + k0 + q * 4);
            As[q * 4 + 0][r] = av.x;
            As[q * 4 + 1][r] = av.y;
            As[q * 4 + 2][r] = av.z;
            As[q * 4 + 3][r] = av.w;
        }
        {
            int kb = tid >> 4, c4 = tid & 15;
            int col = colBase + c4 * 4;
            const float* src;
            if (MODE == 1) {
                int c = col >> 6, d = col & 63;
                src = B + ((size_t)c << 14) + ((size_t)(k0 + kb) << 6) + d;
            } else {
                src = B + (size_t)(k0 + kb) * N + col;
            }
            *reinterpret_cast<float4*>(&Bs[kb][c4 * 4]) =
                *reinterpret_cast<const float4*>(src);
        }
        __syncthreads();
#pragma unroll
        for (int kk = 0; kk < 16; kk++) {
            float4 a0 = *reinterpret_cast<const float4*>(&As[kk][ty * 8]);
            float4 a1 = *reinterpret_cast<const float4*>(&As[kk][ty * 8 + 4]);
            float4 b0 = *reinterpret_cast<const float4*>(&Bs[kk][tx * 4]);
            float ar[8] = {a0.x, a0.y, a0.z, a0.w, a1.x, a1.y, a1.z, a1.w};
            float br[4] = {b0.x, b0.y, b0.z, b0.w};
#pragma unroll
            for (int mi = 0; mi < 8; mi++)
#pragma unroll
                for (int ni = 0; ni < 4; ni++)
                    acc[mi][ni] = fmaf(ar[mi], br[ni], acc[mi][ni]);
        }
        __syncthreads();
    }

    float* P = Cpart + (size_t)blockIdx.z * M * N;
#pragma unroll
    for (int mi = 0; mi < 8; mi++) {
        int r = rowBase + ty * 8 + mi;
        *reinterpret_cast<float4*>(P + (size_t)r * N + colBase + tx * 4) =
            make_float4(acc[mi][0], acc[mi][1], acc[mi][2], acc[mi][3]);
    }
}

// ---------------- projection epilogue: sum 2 partials + bias + per-channel l2norm ----------------
// one block per node, 128 threads (thread t = dims [4t,4t+4), channel = t>>4)
__global__ void __launch_bounds__(128) proj_reduce(
    const float4* __restrict__ P, const float4* __restrict__ bvec4,
    float4* __restrict__ z)
{
    int i = blockIdx.x, t = threadIdx.x;
    int lane = t & 31;
    float4 a = P[(size_t)i * 128 + t];
    float4 b = P[(size_t)NN * 128 + (size_t)i * 128 + t];
    float4 bs = bvec4[t];
    float4 v = make_float4(a.x + b.x + bs.x, a.y + b.y + bs.y,
                           a.z + b.z + bs.z, a.w + b.w + bs.w);
    float ss = v.x * v.x + v.y * v.y + v.z * v.z + v.w * v.w;
    ss += __shfl_xor_sync(0xffffffffu, ss, 1);
    ss += __shfl_xor_sync(0xffffffffu, ss, 2);
    ss += __shfl_xor_sync(0xffffffffu, ss, 4);
    ss += __shfl_xor_sync(0xffffffffu, ss, 8);
    (void)lane;
    float sc = rsqrtf(fmaxf(ss, 1e-12f));
    z[(size_t)i * 128 + t] = make_float4(v.x * sc, v.y * sc, v.z * sc, v.w * sc);
}

// ---------------- output epilogue: sum 4 partials + bias ----------------
__global__ void out_reduce(const float4* __restrict__ P,
                           const float4* __restrict__ bias,
                           float4* __restrict__ out)
{
    int i = blockIdx.x * 256 + threadIdx.x;   // NN*OUTD/4 = 131072
    if (i >= NN * OUTD / 4) return;
    const int S = NN * OUTD / 4;
    float4 a = P[i], b = P[i + S], c = P[i + 2 * S], d = P[i + 3 * S];
    float4 bs = bias[i & (OUTD / 4 - 1)];
    out[i] = make_float4(a.x + b.x + c.x + d.x + bs.x,
                         a.y + b.y + c.y + d.y + bs.y,
                         a.z + b.z + c.z + d.z + bs.z,
                         a.w + b.w + c.w + d.w + bs.w);
}

// ---------------- fused routing iteration, batched 8 edges / 2 barriers ----------------
__global__ void __launch_bounds__(128) route_iter(const float4* __restrict__ zsrc,
                                                  float4* __restrict__ zdst)
{
    int i = blockIdx.x;
    int t = threadIdx.x;
    int lane = t & 31, w = t >> 5;
    int half = lane >> 4;
    int c = t >> 4;
    __shared__ float s_sc[8][8];
    __shared__ float s_a[8][8];

    float4 zi = zsrc[(size_t)i * 128 + t];
    float4 acc = make_float4(0.f, 0.f, 0.f, 0.f);
    int cnt = g_cnt[i];
    const int* cols = g_colpad + i * PAD;

    for (int e0 = 0; e0 < cnt; e0 += 8) {
        int m = cnt - e0;
        float4 zj[8];
#pragma unroll
        for (int k = 0; k < 8; k++) {
            zj[k] = make_float4(0.f, 0.f, 0.f, 0.f);
            if (k < m) {
                int j = cols[e0 + k];
                zj[k] = zsrc[(size_t)j * 128 + t];
            }
        }
#pragma unroll
        for (int k = 0; k < 8; k++) {
            float p = zi.x * zj[k].x + zi.y * zj[k].y + zi.z * zj[k].z + zi.w * zj[k].w;
            p += __shfl_xor_sync(0xffffffffu, p, 1);
            p += __shfl_xor_sync(0xffffffffu, p, 2);
            p += __shfl_xor_sync(0xffffffffu, p, 4);
            p += __shfl_xor_sync(0xffffffffu, p, 8);
            if ((lane & 15) == k) s_sc[k][2 * w + half] = p;
        }
        __syncthreads();
        if (w == 0) {
            int e = lane >> 2, g = lane & 3;
            float v0 = s_sc[e][2 * g], v1 = s_sc[e][2 * g + 1];
            float mx = fmaxf(v0, v1);
            mx = fmaxf(mx, __shfl_xor_sync(0xffffffffu, mx, 1));
            mx = fmaxf(mx, __shfl_xor_sync(0xffffffffu, mx, 2));
            float ex0 = __expf(v0 - mx), ex1 = __expf(v1 - mx);
            float sm = ex0 + ex1;
            sm += __shfl_xor_sync(0xffffffffu, sm, 1);
            sm += __shfl_xor_sync(0xffffffffu, sm, 2);
            float inv = 1.0f / sm;
            s_a[e][2 * g]     = ex0 * inv;
            s_a[e][2 * g + 1] = ex1 * inv;
        }
        __syncthreads();
#pragma unroll
        for (int k = 0; k < 8; k++) {
            float a = s_a[k][c];
            acc.x = fmaf(a, zj[k].x, acc.x);
            acc.y = fmaf(a, zj[k].y, acc.y);
            acc.z = fmaf(a, zj[k].z, acc.z);
            acc.w = fmaf(a, zj[k].w, acc.w);
        }
    }

    float4 zn = make_float4(zi.x + acc.x, zi.y + acc.y, zi.z + acc.z, zi.w + acc.w);
    float ss = zn.x * zn.x + zn.y * zn.y + zn.z * zn.z + zn.w * zn.w;
    ss += __shfl_xor_sync(0xffffffffu, ss, 1);
    ss += __shfl_xor_sync(0xffffffffu, ss, 2);
    ss += __shfl_xor_sync(0xffffffffu, ss, 4);
    ss += __shfl_xor_sync(0xffffffffu, ss, 8);
    float sc = rsqrtf(fmaxf(ss, 1e-12f));
    zdst[(size_t)i * 128 + t] = make_float4(zn.x * sc, zn.y * sc, zn.z * sc, zn.w * sc);
}

// ---------------- launch ----------------
extern "C" void kernel_launch(void* const* d_in, const int* in_sizes, int n_in,
                              void* d_out, int out_size) {
    const float* features = (const float*)d_in[0];   // [4096,256]
    const float* adj      = (const float*)d_in[1];   // [4096,4096]
    const float* W        = (const float*)d_in[2];   // [8,256,64]
    const float* bvec     = (const float*)d_in[3];   // [8,1,64] flat [512]
    const float* W_o      = (const float*)d_in[4];   // [512,128]
    const float* bias     = (const float*)d_in[5];   // [1,128]
    float* out            = (float*)d_out;           // [4096,128]

    float *pzA = nullptr, *pzB = nullptr, *pP = nullptr;
    cudaGetSymbolAddress((void**)&pzA, g_zA);
    cudaGetSymbolAddress((void**)&pzB, g_zB);
    cudaGetSymbolAddress((void**)&pP,  g_part);

    // adjacency -> padded neighbor lists (single DRAM pass, deterministic order)
    build_adj<<<NN / 8, 256>>>(adj);

    // projection: split-K=2 GEMM -> partials, then fused (sum + bias + l2norm)
    gemm128x64<1><<<dim3(CD / 64, NN / 128, 2), 256>>>(
        features, W, pP, NN, CD, IN_DIM, IN_DIM / 2);
    proj_reduce<<<NN, 128>>>((const float4*)pP, (const float4*)bvec, (float4*)pzA);

    // 4 fused routing iterations (ping-pong, final z in zA)
    route_iter<<<NN, 128>>>((const float4*)pzA, (float4*)pzB);
    route_iter<<<NN, 128>>>((const float4*)pzB, (float4*)pzA);
    route_iter<<<NN, 128>>>((const float4*)pzA, (float4*)pzB);
    route_iter<<<NN, 128>>>((const float4*)pzB, (float4*)pzA);

    // output: split-K=4 GEMM -> partials, then fused (sum + bias)
    gemm128x64<0><<<dim3(OUTD / 64, NN / 128, 4), 256>>>(
        pzA, W_o, pP, NN, OUTD, CD, CD / 4);
    out_reduce<<<(NN * OUTD / 4 + 255) / 256, 256>>>(
        (const float4*)pP, (const float4*)bias, (float4*)out);
}

// round 5
// speedup vs baseline: 3.0711x; 1.0069x over previous
#include <cuda_runtime.h>
#include <cuda_fp16.h>
#include <cstdint>
#include <math.h>

#define NN      4096
#define IN_DIM  256
#define CD      512
#define OUTD    128
#define PAD     128      // max neighbors kept per row (mean deg ~41)
#define EB      16       // edges per batch in route_iter

// ---------------- device scratch (no allocations allowed) ----------------
__device__ int   g_cnt[NN];
__device__ int   g_colpad[NN * PAD];
__device__ float g_zA[(size_t)NN * CD];          // final fp32 z for output GEMM
__device__ float g_part[(size_t)2 * NN * CD];    // split-K partials (16MB)
__device__ uint2 g_h16A[(size_t)NN * 128];       // fp16 z ping  [N][512 halfs]
__device__ uint2 g_h16B[(size_t)NN * 128];       // fp16 z pong

// ---------------- single-pass adjacency -> padded column lists ----------------
__global__ void build_adj(const float* __restrict__ adj) {
    int row  = blockIdx.x * 8 + (threadIdx.x >> 5);
    int lane = threadIdx.x & 31;
    const float* r = adj + (size_t)row * NN;
    int* dst = g_colpad + row * PAD;
    int base = 0;
    for (int j0 = 0; j0 < NN; j0 += 32) {
        int j = j0 + lane;
        bool v = r[j] > 0.0f;
        unsigned m = __ballot_sync(0xffffffffu, v);
        if (v) {
            int pos = base + __popc(m & ((1u << lane) - 1u));
            if (pos < PAD) dst[pos] = j;
        }
        base += __popc(m);
    }
    if (lane == 0) g_cnt[row] = base < PAD ? base : PAD;
}

// ---------------- GEMM: BM=128 BN=64 BK=16, split-K, partials out ----------------
// MODE 0: B dense row-major [K,N].  MODE 1: B column col=c*64+d maps to W[c,k,d].
template <int MODE>
__global__ void __launch_bounds__(256) gemm128x64(
    const float* __restrict__ A, const float* __restrict__ B,
    float* __restrict__ Cpart, int M, int N, int K, int kSplit)
{
    __shared__ float As[16][132];
    __shared__ float Bs[16][64];
    int tid = threadIdx.x;
    int rowBase = blockIdx.y * 128;
    int colBase = blockIdx.x * 64;
    int kBeg = blockIdx.z * kSplit;
    int kEnd = kBeg + kSplit;
    int tx = tid & 15, ty = tid >> 4;
    float acc[8][4] = {};

    for (int k0 = kBeg; k0 < kEnd; k0 += 16) {
#pragma unroll
        for (int h = 0; h < 2; h++) {
            int F = tid + h * 256;
            int r = F >> 2, q = F & 3;
            float4 av = *reinterpret_cast<const float4*>(
                A + (size_t)(rowBase + r) * K + k0 + q * 4);
            As[q * 4 + 0][r] = av.x;
            As[q * 4 + 1][r] = av.y;
            As[q * 4 + 2][r] = av.z;
            As[q * 4 + 3][r] = av.w;
        }
        {
            int kb = tid >> 4, c4 = tid & 15;
            int col = colBase + c4 * 4;
            const float* src;
            if (MODE == 1) {
                int c = col >> 6, d = col & 63;
                src = B + ((size_t)c << 14) + ((size_t)(k0 + kb) << 6) + d;
            } else {
                src = B + (size_t)(k0 + kb) * N + col;
            }
            *reinterpret_cast<float4*>(&Bs[kb][c4 * 4]) =
                *reinterpret_cast<const float4*>(src);
        }
        __syncthreads();
#pragma unroll
        for (int kk = 0; kk < 16; kk++) {
            float4 a0 = *reinterpret_cast<const float4*>(&As[kk][ty * 8]);
            float4 a1 = *reinterpret_cast<const float4*>(&As[kk][ty * 8 + 4]);
            float4 b0 = *reinterpret_cast<const float4*>(&Bs[kk][tx * 4]);
            float ar[8] = {a0.x, a0.y, a0.z, a0.w, a1.x, a1.y, a1.z, a1.w};
            float br[4] = {b0.x, b0.y, b0.z, b0.w};
#pragma unroll
            for (int mi = 0; mi < 8; mi++)
#pragma unroll
                for (int ni = 0; ni < 4; ni++)
                    acc[mi][ni] = fmaf(ar[mi], br[ni], acc[mi][ni]);
        }
        __syncthreads();
    }

    float* P = Cpart + (size_t)blockIdx.z * M * N;
#pragma unroll
    for (int mi = 0; mi < 8; mi++) {
        int r = rowBase + ty * 8 + mi;
        *reinterpret_cast<float4*>(P + (size_t)r * N + colBase + tx * 4) =
            make_float4(acc[mi][0], acc[mi][1], acc[mi][2], acc[mi][3]);
    }
}

// ---------------- projection epilogue: sum 2 partials + bias + l2norm -> fp16 ----------------
__global__ void __launch_bounds__(128) proj_reduce(
    const float4* __restrict__ P, const float4* __restrict__ bvec4,
    uint2* __restrict__ z16)
{
    int i = blockIdx.x, t = threadIdx.x;
    float4 a = P[(size_t)i * 128 + t];
    float4 b = P[(size_t)NN * 128 + (size_t)i * 128 + t];
    float4 bs = bvec4[t];
    float4 v = make_float4(a.x + b.x + bs.x, a.y + b.y + bs.y,
                           a.z + b.z + bs.z, a.w + b.w + bs.w);
    float ss = v.x * v.x + v.y * v.y + v.z * v.z + v.w * v.w;
    ss += __shfl_xor_sync(0xffffffffu, ss, 1);
    ss += __shfl_xor_sync(0xffffffffu, ss, 2);
    ss += __shfl_xor_sync(0xffffffffu, ss, 4);
    ss += __shfl_xor_sync(0xffffffffu, ss, 8);
    float sc = rsqrtf(fmaxf(ss, 1e-12f));
    __half2 h0 = __floats2half2_rn(v.x * sc, v.y * sc);
    __half2 h1 = __floats2half2_rn(v.z * sc, v.w * sc);
    z16[(size_t)i * 128 + t] =
        make_uint2(*reinterpret_cast<unsigned int*>(&h0),
                   *reinterpret_cast<unsigned int*>(&h1));
}

// ---------------- output epilogue: sum 4 partials + bias ----------------
__global__ void out_reduce(const float4* __restrict__ P,
                           const float4* __restrict__ bias,
                           float4* __restrict__ out)
{
    int i = blockIdx.x * 256 + threadIdx.x;
    if (i >= NN * OUTD / 4) return;
    const int S = NN * OUTD / 4;
    float4 a = P[i], b = P[i + S], c = P[i + 2 * S], d = P[i + 3 * S];
    float4 bs = bias[i & (OUTD / 4 - 1)];
    out[i] = make_float4(a.x + b.x + c.x + d.x + bs.x,
                         a.y + b.y + c.y + d.y + bs.y,
                         a.z + b.z + c.z + d.z + bs.z,
                         a.w + b.w + c.w + d.w + bs.w);
}

// ---------------- fused routing iteration: fp16 storage, fp32 compute ----------------
// 128 threads: thread t owns dims [4t,4t+4); channel c = t>>4 (16 lanes per channel).
// 16 edges per batch, 2 barriers per batch, softmax fully parallel across the block.
template <bool LAST>
__global__ void __launch_bounds__(128) route_iter(
    const uint2* __restrict__ zsrc, uint2* __restrict__ zdst,
    float4* __restrict__ zfin)
{
    int i = blockIdx.x;
    int t = threadIdx.x;
    int lane = t & 31;
    int c = t >> 4;
    __shared__ float s_sc[EB][9];   // padded: conflict-free predicated stores
    __shared__ float s_a[EB][8];

    uint2 ziu = zsrc[(size_t)i * 128 + t];
    float2 zi0 = __half22float2(*reinterpret_cast<const __half2*>(&ziu.x));
    float2 zi1 = __half22float2(*reinterpret_cast<const __half2*>(&ziu.y));
    float4 acc = make_float4(0.f, 0.f, 0.f, 0.f);
    int cnt = g_cnt[i];
    const int* cols = g_colpad + i * PAD;

    for (int e0 = 0; e0 < cnt; e0 += EB) {
        int m = cnt - e0;
        uint2 zj[EB];
#pragma unroll
        for (int k = 0; k < EB; k++) {
            zj[k] = make_uint2(0u, 0u);     // fp16 zeros
            if (k < m) {
                int j = cols[e0 + k];
                zj[k] = zsrc[(size_t)j * 128 + t];
            }
        }
        // per-channel dots (reduce within 16-lane channel group)
#pragma unroll
        for (int k = 0; k < EB; k++) {
            float2 f0 = __half22float2(*reinterpret_cast<const __half2*>(&zj[k].x));
            float2 f1 = __half22float2(*reinterpret_cast<const __half2*>(&zj[k].y));
            float p = zi0.x * f0.x + zi0.y * f0.y + zi1.x * f1.x + zi1.y * f1.y;
            p += __shfl_xor_sync(0xffffffffu, p, 1);
            p += __shfl_xor_sync(0xffffffffu, p, 2);
            p += __shfl_xor_sync(0xffffffffu, p, 4);
            p += __shfl_xor_sync(0xffffffffu, p, 8);
            if ((lane & 15) == k) s_sc[k][c] = p;
        }
        __syncthreads();
        // fully parallel 8-way channel softmax: thread -> (edge,channel)=(t>>3, t&7)
        {
            int e = t >> 3, ch = t & 7;
            float v = s_sc[e][ch];
            float mx = v;
            mx = fmaxf(mx, __shfl_xor_sync(0xffffffffu, mx, 1));
            mx = fmaxf(mx, __shfl_xor_sync(0xffffffffu, mx, 2));
            mx = fmaxf(mx, __shfl_xor_sync(0xffffffffu, mx, 4));
            float ex = __expf(v - mx);
            float sm = ex;
            sm += __shfl_xor_sync(0xffffffffu, sm, 1);
            sm += __shfl_xor_sync(0xffffffffu, sm, 2);
            sm += __shfl_xor_sync(0xffffffffu, sm, 4);
            s_a[e][ch] = ex / sm;
        }
        __syncthreads();
        // aggregate (zj = 0 for padded edges -> no contribution)
#pragma unroll
        for (int k = 0; k < EB; k++) {
            float a = s_a[k][c];
            float2 f0 = __half22float2(*reinterpret_cast<const __half2*>(&zj[k].x));
            float2 f1 = __half22float2(*reinterpret_cast<const __half2*>(&zj[k].y));
            acc.x = fmaf(a, f0.x, acc.x);
            acc.y = fmaf(a, f0.y, acc.y);
            acc.z = fmaf(a, f1.x, acc.z);
            acc.w = fmaf(a, f1.y, acc.w);
        }
        // next batch's s_sc writes are fenced from this batch's s_a reads by
        // program order + the next barrier pair.
    }

    // residual + per-channel l2norm (fp32)
    float4 zn = make_float4(zi0.x + acc.x, zi0.y + acc.y, zi1.x + acc.z, zi1.y + acc.w);
    float ss = zn.x * zn.x + zn.y * zn.y + zn.z * zn.z + zn.w * zn.w;
    ss += __shfl_xor_sync(0xffffffffu, ss, 1);
    ss += __shfl_xor_sync(0xffffffffu, ss, 2);
    ss += __shfl_xor_sync(0xffffffffu, ss, 4);
    ss += __shfl_xor_sync(0xffffffffu, ss, 8);
    float sc = rsqrtf(fmaxf(ss, 1e-12f));
    if (LAST) {
        zfin[(size_t)i * 128 + t] =
            make_float4(zn.x * sc, zn.y * sc, zn.z * sc, zn.w * sc);
    } else {
        __half2 h0 = __floats2half2_rn(zn.x * sc, zn.y * sc);
        __half2 h1 = __floats2half2_rn(zn.z * sc, zn.w * sc);
        zdst[(size_t)i * 128 + t] =
            make_uint2(*reinterpret_cast<unsigned int*>(&h0),
                       *reinterpret_cast<unsigned int*>(&h1));
    }
}

// ---------------- launch ----------------
extern "C" void kernel_launch(void* const* d_in, const int* in_sizes, int n_in,
                              void* d_out, int out_size) {
    const float* features = (const float*)d_in[0];   // [4096,256]
    const float* adj      = (const float*)d_in[1];   // [4096,4096]
    const float* W        = (const float*)d_in[2];   // [8,256,64]
    const float* bvec     = (const float*)d_in[3];   // [8,1,64] flat [512]
    const float* W_o      = (const float*)d_in[4];   // [512,128]
    const float* bias     = (const float*)d_in[5];   // [1,128]
    float* out            = (float*)d_out;           // [4096,128]

    float *pzA = nullptr, *pP = nullptr;
    uint2 *pA16 = nullptr, *pB16 = nullptr;
    cudaGetSymbolAddress((void**)&pzA,  g_zA);
    cudaGetSymbolAddress((void**)&pP,   g_part);
    cudaGetSymbolAddress((void**)&pA16, g_h16A);
    cudaGetSymbolAddress((void**)&pB16, g_h16B);

    // adjacency -> padded neighbor lists (single DRAM pass, deterministic order)
    build_adj<<<NN / 8, 256>>>(adj);

    // projection: split-K=2 GEMM -> partials, then fused sum+bias+l2norm -> fp16
    gemm128x64<1><<<dim3(CD / 64, NN / 128, 2), 256>>>(
        features, W, pP, NN, CD, IN_DIM, IN_DIM / 2);
    proj_reduce<<<NN, 128>>>((const float4*)pP, (const float4*)bvec, pA16);

    // 4 fused routing iterations (fp16 state, fp32 math; final -> fp32 zA)
    route_iter<false><<<NN, 128>>>(pA16, pB16, nullptr);
    route_iter<false><<<NN, 128>>>(pB16, pA16, nullptr);
    route_iter<false><<<NN, 128>>>(pA16, pB16, nullptr);
    route_iter<true ><<<NN, 128>>>(pB16, nullptr, (float4*)pzA);

    // output: split-K=4 GEMM -> partials, then fused sum+bias
    gemm128x64<0><<<dim3(OUTD / 64, NN / 128, 4), 256>>>(
        pzA, W_o, pP, NN, OUTD, CD, CD / 4);
    out_reduce<<<(NN * OUTD / 4 + 255) / 256, 256>>>(
        (const float4*)pP, (const float4*)bias, (float4*)out);
}

// round 6
// speedup vs baseline: 3.0745x; 1.0011x over previous
#include <cuda_runtime.h>
#include <cuda_fp16.h>
#include <cstdint>
#include <math.h>

#define NN      4096
#define IN_DIM  256
#define CD      512
#define OUTD    128
#define PAD     128      // max neighbors kept per row (mean deg ~41)
#define EB      4        // edges per batch in route_iter (warp version)

// ---------------- device scratch (no allocations allowed) ----------------
__device__ int   g_cnt[NN];
__device__ int   g_colpad[NN * PAD];
__device__ float g_zA[(size_t)NN * CD];          // final fp32 z for output GEMM
__device__ float g_part[(size_t)2 * NN * CD];    // split-K partials (16MB)
__device__ uint4 g_h16A[(size_t)NN * 64];        // fp16 z ping  [N][512 halfs] as uint4
__device__ uint4 g_h16B[(size_t)NN * 64];        // fp16 z pong

// ---------------- single-pass adjacency -> padded column lists ----------------
__global__ void build_adj(const float* __restrict__ adj) {
    int row  = blockIdx.x * 8 + (threadIdx.x >> 5);
    int lane = threadIdx.x & 31;
    const float* r = adj + (size_t)row * NN;
    int* dst = g_colpad + row * PAD;
    int base = 0;
    for (int j0 = 0; j0 < NN; j0 += 32) {
        int j = j0 + lane;
        bool v = r[j] > 0.0f;
        unsigned m = __ballot_sync(0xffffffffu, v);
        if (v) {
            int pos = base + __popc(m & ((1u << lane) - 1u));
            if (pos < PAD) dst[pos] = j;
        }
        base += __popc(m);
    }
    if (lane == 0) g_cnt[row] = base < PAD ? base : PAD;
}

// ---------------- GEMM: BM=128 BN=64 BK=16, split-K, partials out ----------------
// MODE 0: B dense row-major [K,N].  MODE 1: B column col=c*64+d maps to W[c,k,d].
template <int MODE>
__global__ void __launch_bounds__(256) gemm128x64(
    const float* __restrict__ A, const float* __restrict__ B,
    float* __restrict__ Cpart, int M, int N, int K, int kSplit)
{
    __shared__ float As[16][132];
    __shared__ float Bs[16][64];
    int tid = threadIdx.x;
    int rowBase = blockIdx.y * 128;
    int colBase = blockIdx.x * 64;
    int kBeg = blockIdx.z * kSplit;
    int kEnd = kBeg + kSplit;
    int tx = tid & 15, ty = tid >> 4;
    float acc[8][4] = {};

    for (int k0 = kBeg; k0 < kEnd; k0 += 16) {
#pragma unroll
        for (int h = 0; h < 2; h++) {
            int F = tid + h * 256;
            int r = F >> 2, q = F & 3;
            float4 av = *reinterpret_cast<const float4*>(
                A + (size_t)(rowBase + r) * K + k0 + q * 4);
            As[q * 4 + 0][r] = av.x;
            As[q * 4 + 1][r] = av.y;
            As[q * 4 + 2][r] = av.z;
            As[q * 4 + 3][r] = av.w;
        }
        {
            int kb = tid >> 4, c4 = tid & 15;
            int col = colBase + c4 * 4;
            const float* src;
            if (MODE == 1) {
                int c = col >> 6, d = col & 63;
                src = B + ((size_t)c << 14) + ((size_t)(k0 + kb) << 6) + d;
            } else {
                src = B + (size_t)(k0 + kb) * N + col;
            }
            *reinterpret_cast<float4*>(&Bs[kb][c4 * 4]) =
                *reinterpret_cast<const float4*>(src);
        }
        __syncthreads();
#pragma unroll
        for (int kk = 0; kk < 16; kk++) {
            float4 a0 = *reinterpret_cast<const float4*>(&As[kk][ty * 8]);
            float4 a1 = *reinterpret_cast<const float4*>(&As[kk][ty * 8 + 4]);
            float4 b0 = *reinterpret_cast<const float4*>(&Bs[kk][tx * 4]);
            float ar[8] = {a0.x, a0.y, a0.z, a0.w, a1.x, a1.y, a1.z, a1.w};
            float br[4] = {b0.x, b0.y, b0.z, b0.w};
#pragma unroll
            for (int mi = 0; mi < 8; mi++)
#pragma unroll
                for (int ni = 0; ni < 4; ni++)
                    acc[mi][ni] = fmaf(ar[mi], br[ni], acc[mi][ni]);
        }
        __syncthreads();
    }

    float* P = Cpart + (size_t)blockIdx.z * M * N;
#pragma unroll
    for (int mi = 0; mi < 8; mi++) {
        int r = rowBase + ty * 8 + mi;
        *reinterpret_cast<float4*>(P + (size_t)r * N + colBase + tx * 4) =
            make_float4(acc[mi][0], acc[mi][1], acc[mi][2], acc[mi][3]);
    }
}

// ---------------- projection epilogue: sum 2 partials + bias + l2norm -> fp16 ----------------
__global__ void __launch_bounds__(128) proj_reduce(
    const float4* __restrict__ P, const float4* __restrict__ bvec4,
    uint2* __restrict__ z16)
{
    int i = blockIdx.x, t = threadIdx.x;
    float4 a = P[(size_t)i * 128 + t];
    float4 b = P[(size_t)NN * 128 + (size_t)i * 128 + t];
    float4 bs = bvec4[t];
    float4 v = make_float4(a.x + b.x + bs.x, a.y + b.y + bs.y,
                           a.z + b.z + bs.z, a.w + b.w + bs.w);
    float ss = v.x * v.x + v.y * v.y + v.z * v.z + v.w * v.w;
    ss += __shfl_xor_sync(0xffffffffu, ss, 1);
    ss += __shfl_xor_sync(0xffffffffu, ss, 2);
    ss += __shfl_xor_sync(0xffffffffu, ss, 4);
    ss += __shfl_xor_sync(0xffffffffu, ss, 8);
    float sc = rsqrtf(fmaxf(ss, 1e-12f));
    __half2 h0 = __floats2half2_rn(v.x * sc, v.y * sc);
    __half2 h1 = __floats2half2_rn(v.z * sc, v.w * sc);
    z16[(size_t)i * 128 + t] =
        make_uint2(*reinterpret_cast<unsigned int*>(&h0),
                   *reinterpret_cast<unsigned int*>(&h1));
}

// ---------------- output epilogue: sum 4 partials + bias ----------------
__global__ void out_reduce(const float4* __restrict__ P,
                           const float4* __restrict__ bias,
                           float4* __restrict__ out)
{
    int i = blockIdx.x * 256 + threadIdx.x;
    if (i >= NN * OUTD / 4) return;
    const int S = NN * OUTD / 4;
    float4 a = P[i], b = P[i + S], c = P[i + 2 * S], d = P[i + 3 * S];
    float4 bs = bias[i & (OUTD / 4 - 1)];
    out[i] = make_float4(a.x + b.x + c.x + d.x + bs.x,
                         a.y + b.y + c.y + d.y + bs.y,
                         a.z + b.z + c.z + d.z + bs.z,
                         a.w + b.w + c.w + d.w + bs.w);
}

// ---------------- helpers: fp16x16 <-> fp32x16 ----------------
__device__ __forceinline__ void cvt8(uint4 u, float* f) {
    const unsigned int* p = &u.x;
#pragma unroll
    for (int q = 0; q < 4; q++) {
        float2 v = __half22float2(*reinterpret_cast<const __half2*>(&p[q]));
        f[2 * q]     = v.x;
        f[2 * q + 1] = v.y;
    }
}

// ---------------- warp-per-node routing: no barriers, no shared memory ----------------
// Warp = one node. Lane l owns dims [16l, 16l+16); channel c = l>>2 (4 lanes x 16 dims).
// Per edge: dot reduce = 2 shuffles (xor 1,2); channel softmax = butterfly xor 4,8,16.
template <bool LAST>
__global__ void __launch_bounds__(128) route_iter(
    const uint4* __restrict__ zsrc, uint4* __restrict__ zdst,
    float4* __restrict__ zfin)
{
    int i    = blockIdx.x * 4 + (threadIdx.x >> 5);
    int lane = threadIdx.x & 31;

    // load zi (16 dims per lane) -> fp32
    float zi[16];
    {
        uint4 u0 = zsrc[(size_t)i * 64 + 2 * lane];
        uint4 u1 = zsrc[(size_t)i * 64 + 2 * lane + 1];
        cvt8(u0, zi);
        cvt8(u1, zi + 8);
    }
    float acc[16];
#pragma unroll
    for (int d = 0; d < 16; d++) acc[d] = 0.0f;

    int cnt = g_cnt[i];
    const int* cols = g_colpad + i * PAD;

    for (int e0 = 0; e0 < cnt; e0 += EB) {
        int m = cnt - e0;
        uint4 u[EB][2];
#pragma unroll
        for (int k = 0; k < EB; k++) {
            u[k][0] = make_uint4(0u, 0u, 0u, 0u);
            u[k][1] = make_uint4(0u, 0u, 0u, 0u);
            if (k < m) {
                int j = cols[e0 + k];
                u[k][0] = zsrc[(size_t)j * 64 + 2 * lane];
                u[k][1] = zsrc[(size_t)j * 64 + 2 * lane + 1];
            }
        }
#pragma unroll
        for (int k = 0; k < EB; k++) {
            float zj[16];
            cvt8(u[k][0], zj);
            cvt8(u[k][1], zj + 8);
            // per-channel dot: 16 dims in-lane, then reduce over 4-lane group
            float p = 0.0f;
#pragma unroll
            for (int d = 0; d < 16; d++) p = fmaf(zi[d], zj[d], p);
            p += __shfl_xor_sync(0xffffffffu, p, 1);
            p += __shfl_xor_sync(0xffffffffu, p, 2);
            // 8-way channel softmax via butterfly across groups (xor 4,8,16)
            float mx = p;
            mx = fmaxf(mx, __shfl_xor_sync(0xffffffffu, mx, 4));
            mx = fmaxf(mx, __shfl_xor_sync(0xffffffffu, mx, 8));
            mx = fmaxf(mx, __shfl_xor_sync(0xffffffffu, mx, 16));
            float ex = __expf(p - mx);
            float sm = ex;
            sm += __shfl_xor_sync(0xffffffffu, sm, 4);
            sm += __shfl_xor_sync(0xffffffffu, sm, 8);
            sm += __shfl_xor_sync(0xffffffffu, sm, 16);
            float a = ex / sm;   // padded edge: zj=0 -> contributes a*0 = 0
            // aggregate
#pragma unroll
            for (int d = 0; d < 16; d++) acc[d] = fmaf(a, zj[d], acc[d]);
        }
    }

    // residual + per-channel l2norm (channel = 4-lane group)
    float zn[16];
    float ss = 0.0f;
#pragma unroll
    for (int d = 0; d < 16; d++) {
        zn[d] = zi[d] + acc[d];
        ss = fmaf(zn[d], zn[d], ss);
    }
    ss += __shfl_xor_sync(0xffffffffu, ss, 1);
    ss += __shfl_xor_sync(0xffffffffu, ss, 2);
    float sc = rsqrtf(fmaxf(ss, 1e-12f));

    if (LAST) {
        // fp32 output row: thread owns float4 indices 4l..4l+3 of 128
#pragma unroll
        for (int q = 0; q < 4; q++) {
            zfin[(size_t)i * 128 + 4 * lane + q] =
                make_float4(zn[4 * q] * sc, zn[4 * q + 1] * sc,
                            zn[4 * q + 2] * sc, zn[4 * q + 3] * sc);
        }
    } else {
        uint4 o[2];
        unsigned int* po = &o[0].x;
#pragma unroll
        for (int q = 0; q < 8; q++) {
            __half2 h = __floats2half2_rn(zn[2 * q] * sc, zn[2 * q + 1] * sc);
            po[q] = *reinterpret_cast<unsigned int*>(&h);
        }
        zdst[(size_t)i * 64 + 2 * lane]     = o[0];
        zdst[(size_t)i * 64 + 2 * lane + 1] = o[1];
    }
}

// ---------------- launch ----------------
extern "C" void kernel_launch(void* const* d_in, const int* in_sizes, int n_in,
                              void* d_out, int out_size) {
    const float* features = (const float*)d_in[0];   // [4096,256]
    const float* adj      = (const float*)d_in[1];   // [4096,4096]
    const float* W        = (const float*)d_in[2];   // [8,256,64]
    const float* bvec     = (const float*)d_in[3];   // [8,1,64] flat [512]
    const float* W_o      = (const float*)d_in[4];   // [512,128]
    const float* bias     = (const float*)d_in[5];   // [1,128]
    float* out            = (float*)d_out;           // [4096,128]

    float *pzA = nullptr, *pP = nullptr;
    uint4 *pA16 = nullptr, *pB16 = nullptr;
    cudaGetSymbolAddress((void**)&pzA,  g_zA);
    cudaGetSymbolAddress((void**)&pP,   g_part);
    cudaGetSymbolAddress((void**)&pA16, g_h16A);
    cudaGetSymbolAddress((void**)&pB16, g_h16B);

    // adjacency -> padded neighbor lists (single DRAM pass, deterministic order)
    build_adj<<<NN / 8, 256>>>(adj);

    // projection: split-K=2 GEMM -> partials, then fused sum+bias+l2norm -> fp16
    gemm128x64<1><<<dim3(CD / 64, NN / 128, 2), 256>>>(
        features, W, pP, NN, CD, IN_DIM, IN_DIM / 2);
    proj_reduce<<<NN, 128>>>((const float4*)pP, (const float4*)bvec, (uint2*)pA16);

    // 4 warp-per-node routing iterations (fp16 state, fp32 math; final -> fp32 zA)
    route_iter<false><<<NN / 4, 128>>>(pA16, pB16, nullptr);
    route_iter<false><<<NN / 4, 128>>>(pB16, pA16, nullptr);
    route_iter<false><<<NN / 4, 128>>>(pA16, pB16, nullptr);
    route_iter<true ><<<NN / 4, 128>>>(pB16, nullptr, (float4*)pzA);

    // output: split-K=4 GEMM -> partials, then fused sum+bias
    gemm128x64<0><<<dim3(OUTD / 64, NN / 128, 4), 256>>>(
        pzA, W_o, pP, NN, OUTD, CD, CD / 4);
    out_reduce<<<(NN * OUTD / 4 + 255) / 256, 256>>>(
        (const float4*)pP, (const float4*)bias, (float4*)out);
}